// round 14
// baseline (speedup 1.0000x reference)
#include <cuda_runtime.h>
#include <cuda_bf16.h>
#include <math.h>
#include <cstdint>

#define TKN    200704
#define QSCALE 0.17677669529663688f
#define GPERS  304              // persistent grid: 2 CTAs/SM x 152 SMs

// Scratch (allocation-free): bf16 activations + pre-converted weights
__device__ __nv_bfloat16 g_buf1[200704 * 384];  // qkv [T,288] then fc1-out [T,384]
__device__ __nv_bfloat16 g_buf2[200704 * 96];   // attn-out [T,96]
__device__ __nv_bfloat16 g_buf3[200704 * 96];   // fused-LN2 out [T,96]
__device__ __nv_bfloat16 g_wbuf[110592];        // qkv_w | proj_w | fc1_w | fc2_w (bf16)
__device__ __nv_bfloat16 g_bias[4 * 3 * 64 * 64]; // combined bias+mask per window class

#define WOFF_QKV  0
#define WOFF_PROJ 27648
#define WOFF_FC1  36864
#define WOFF_FC2  73728

// ---------------------------------------------------------------------------
// PTX helpers
// ---------------------------------------------------------------------------
__device__ __forceinline__ uint32_t smem_u32(const void* p) {
    uint32_t a;
    asm("{ .reg .u64 t; cvta.to.shared.u64 t, %1; cvt.u32.u64 %0, t; }" : "=r"(a) : "l"(p));
    return a;
}
__device__ __forceinline__ void cp16(uint32_t dst, const void* src) {
    asm volatile("cp.async.cg.shared.global [%0], [%1], 16;" :: "r"(dst), "l"(src));
}
#define CP_COMMIT() asm volatile("cp.async.commit_group;" ::: "memory")
__device__ __forceinline__ void ldm_x4(uint32_t& r0, uint32_t& r1, uint32_t& r2, uint32_t& r3,
                                       uint32_t addr) {
    asm volatile("ldmatrix.sync.aligned.m8n8.x4.shared.b16 {%0,%1,%2,%3}, [%4];"
                 : "=r"(r0), "=r"(r1), "=r"(r2), "=r"(r3) : "r"(addr));
}
__device__ __forceinline__ void ldm_x4t(uint32_t& r0, uint32_t& r1, uint32_t& r2, uint32_t& r3,
                                        uint32_t addr) {
    asm volatile("ldmatrix.sync.aligned.m8n8.x4.trans.shared.b16 {%0,%1,%2,%3}, [%4];"
                 : "=r"(r0), "=r"(r1), "=r"(r2), "=r"(r3) : "r"(addr));
}
__device__ __forceinline__ void mma_bf16(float* c, uint32_t a0, uint32_t a1, uint32_t a2,
                                         uint32_t a3, uint32_t b0, uint32_t b1) {
    asm volatile("mma.sync.aligned.m16n8k16.row.col.f32.bf16.bf16.f32 "
                 "{%0,%1,%2,%3}, {%4,%5,%6,%7}, {%8,%9}, {%0,%1,%2,%3};"
                 : "+f"(c[0]), "+f"(c[1]), "+f"(c[2]), "+f"(c[3])
                 : "r"(a0), "r"(a1), "r"(a2), "r"(a3), "r"(b0), "r"(b1));
}
__device__ __forceinline__ uint32_t packbf(float a, float b) {
    __nv_bfloat162 h = __floats2bfloat162_rn(a, b);
    return *reinterpret_cast<uint32_t*>(&h);
}

// ---------------------------------------------------------------------------
// Weight pre-convert fp32 -> bf16
// ---------------------------------------------------------------------------
__global__ void wconv(const float* __restrict__ a, const float* __restrict__ b,
                      const float* __restrict__ c, const float* __restrict__ d,
                      __nv_bfloat16* __restrict__ o) {
    int i = blockIdx.x * 256 + threadIdx.x;
    if (i < 27648)       o[i] = __float2bfloat16(a[i]);
    else if (i < 36864)  o[i] = __float2bfloat16(b[i - 27648]);
    else if (i < 73728)  o[i] = __float2bfloat16(c[i - 36864]);
    else if (i < 110592) o[i] = __float2bfloat16(d[i - 73728]);
}

// ---------------------------------------------------------------------------
// Combined bias table: tab[cls][h][i(64)][j(64)] = rpb + shiftmask, pad -> -1e30
// ---------------------------------------------------------------------------
__device__ __forceinline__ int winlab(int cls, int r, int c) {
    int rh = (cls & 2) ? (r < 4 ? 1 : 2) : 0;
    int rw = (cls & 1) ? (c < 4 ? 1 : 2) : 0;
    return rh * 3 + rw;
}
__global__ void bias_prep(const float* __restrict__ rpb, __nv_bfloat16* __restrict__ tab) {
    int idx = blockIdx.x * 256 + threadIdx.x;
    if (idx >= 4 * 3 * 64 * 64) return;
    int j = idx & 63, i = (idx >> 6) & 63;
    int h = (idx >> 12) % 3, cls = idx >> 12; cls /= 3;
    float v;
    if (j >= 49 || i >= 49) v = -1e30f;
    else {
        int ri = i / 7, ci = i % 7, rj = j / 7, cj = j % 7;
        v = rpb[((ri - rj + 6) * 13 + (ci - cj + 6)) * 3 + h];
        if (winlab(cls, ri, ci) != winlab(cls, rj, cj)) v -= 100.0f;
    }
    tab[idx] = __float2bfloat16(v);
}

// ---------------------------------------------------------------------------
// Persistent pipelined HMMA GEMM (256 thr, 8 warps 4x2, warp 32x48).
// nb-INNER contiguous unit blocks; A resident across NB n-chunks.
// MODE 0: qkv — A tile produced IN-KERNEL by fused LN1 + cyclic-shift gather
//         from fp32 x (passed via resid; LN params via g2/b2).
// MODE 1: proj + residual + fused LN2; MODE 2: fc1+GELU; MODE 3: fc2 accum.
// ---------------------------------------------------------------------------
template <int MODE, int KGLOB, int KCH, int NOUT, int NB>
__global__ void __launch_bounds__(256, 2)
tc_gemm(const __nv_bfloat16* __restrict__ A, const __nv_bfloat16* __restrict__ Wb,
        const float* __restrict__ bias, void* __restrict__ outv,
        const float* __restrict__ resid, const float* __restrict__ g2,
        const float* __restrict__ b2, __nv_bfloat16* __restrict__ ln2out) {
    constexpr int NT = 1568;
    constexpr int NUNITS = NT * NB;
    constexpr int ABYTES = 128 * 104 * 2;
    constexpr int BBYTES = 96 * 104 * 2;
    constexpr int PART_OFF = 2 * ABYTES + 2 * BBYTES;
    extern __shared__ char smem[];
    const uint32_t sbase = smem_u32(smem);
    const uint32_t Ab0 = sbase, Ab1 = sbase + ABYTES;
    const uint32_t Bb0 = sbase + 2 * ABYTES, Bb1 = Bb0 + BBYTES;

    const int tid  = threadIdx.x;
    const int lane = tid & 31;
    const int wid  = tid >> 5;
    const int wm   = wid & 3;
    const int wn   = wid >> 2;

    constexpr int PERCTA = (NUNITS + GPERS - 1) / GPERS;
    const int base    = blockIdx.x * PERCTA;
    int myUnits       = NUNITS - base;
    if (myUnits > PERCTA) myUnits = PERCTA;
    if (myUnits <= 0) return;
    const int mySteps = myUnits * KCH;

    // Fused LN1 + shift-gather A fill (MODE 0): warp w handles rows w*16..+16.
    auto fillA = [&](int tile, uint32_t da) {
        #pragma unroll 1
        for (int rr = 0; rr < 16; rr += 4) {
            #pragma unroll
            for (int q = 0; q < 4; q++) {
                int r   = wid * 16 + rr + q;
                int row = tile * 128 + r;
                int bi  = row / 3136;
                int rem = row % 3136;
                int w   = rem / 49, n = rem % 49;
                int wh = w >> 3, ww = w & 7;
                int r7 = n / 7, c7 = n % 7;
                int sh = wh * 7 + r7 + 3;  if (sh >= 56) sh -= 56;
                int sw = ww * 7 + c7 + 3;  if (sw >= 56) sw -= 56;
                const float* xr = resid + ((size_t)bi * 3136 + sh * 56 + sw) * 96;
                float v0 = __ldg(xr + lane), v1 = __ldg(xr + lane + 32), v2 = __ldg(xr + lane + 64);
                float s  = v0 + v1 + v2;
                float s2 = v0 * v0 + v1 * v1 + v2 * v2;
                #pragma unroll
                for (int o = 16; o; o >>= 1) {
                    s  += __shfl_xor_sync(0xffffffffu, s,  o);
                    s2 += __shfl_xor_sync(0xffffffffu, s2, o);
                }
                float mean = s * (1.0f / 96.0f);
                float var  = s2 * (1.0f / 96.0f) - mean * mean;
                float rs   = rsqrtf(var + 1e-5f);
                __nv_bfloat16 h0 = __float2bfloat16((v0 - mean) * rs * __ldg(g2 + lane)      + __ldg(b2 + lane));
                __nv_bfloat16 h1 = __float2bfloat16((v1 - mean) * rs * __ldg(g2 + lane + 32) + __ldg(b2 + lane + 32));
                __nv_bfloat16 h2 = __float2bfloat16((v2 - mean) * rs * __ldg(g2 + lane + 64) + __ldg(b2 + lane + 64));
                uint32_t rowa = da + (uint32_t)r * 208;
                asm volatile("st.shared.b16 [%0], %1;" :: "r"(rowa + lane * 2),        "h"(*reinterpret_cast<uint16_t*>(&h0)));
                asm volatile("st.shared.b16 [%0], %1;" :: "r"(rowa + (lane + 32) * 2), "h"(*reinterpret_cast<uint16_t*>(&h1)));
                asm volatile("st.shared.b16 [%0], %1;" :: "r"(rowa + (lane + 64) * 2), "h"(*reinterpret_cast<uint16_t*>(&h2)));
            }
        }
    };

    auto issue = [&](int s) {
        const int lu   = s / KCH;
        const int kc   = s % KCH;
        const int u    = base + lu;
        const int tile = u / NB;
        const int nb   = u % NB;
        // B: every step
        {
            const __nv_bfloat16* sb = Wb + (size_t)nb * 96 * KGLOB + kc * 96;
            uint32_t db = (s & 1) ? Bb1 : Bb0;
            #pragma unroll
            for (int i = tid; i < 96 * 12; i += 256) {
                int r = i / 12, c = i % 12;
                cp16(db + r * 208 + c * 16, sb + (size_t)r * KGLOB + c * 8);
            }
        }
        // A via cp.async (non-fused modes only)
        if (MODE != 0) {
            bool needA = (KCH > 1) || (u % NB == 0) || (s == 0);
            if (needA) {
                const __nv_bfloat16* sa = A + (size_t)tile * 128 * KGLOB + kc * 96;
                uint32_t da;
                if (KCH > 1) da = (s & 1) ? Ab1 : Ab0;
                else         da = ((tile & 1) ? Ab1 : Ab0);
                #pragma unroll
                for (int i = tid; i < 128 * 12; i += 256) {
                    int r = i / 12, c = i % 12;
                    cp16(da + r * 208 + c * 16, sa + (size_t)r * KGLOB + c * 8);
                }
            }
        }
    };

    issue(0); CP_COMMIT();

    float acc[2][6][4];

    for (int s = 0; s < mySteps; s++) {
        const int kc   = s % KCH;
        const int u    = base + s / KCH;
        const int tile = u / NB;
        const int nb   = u % NB;
        if (s + 1 < mySteps) {
            issue(s + 1);
            CP_COMMIT();
            asm volatile("cp.async.wait_group 1;" ::: "memory");
        } else {
            asm volatile("cp.async.wait_group 0;" ::: "memory");
        }
        __syncthreads();

        // MODE 0: produce A tile (LN1 + gather) at the first step of each tile
        if (MODE == 0 && ((u % NB) == 0 || s == 0)) {
            fillA(tile, (tile & 1) ? Ab1 : Ab0);
            __syncthreads();
        }

        if (kc == 0) {
            #pragma unroll
            for (int m = 0; m < 2; m++)
                #pragma unroll
                for (int n = 0; n < 6; n++)
                    #pragma unroll
                    for (int v = 0; v < 4; v++) acc[m][n][v] = 0.0f;
        }

        const uint32_t abase = (KCH > 1) ? ((s & 1) ? Ab1 : Ab0)
                                         : ((tile & 1) ? Ab1 : Ab0);
        const uint32_t bbase = (s & 1) ? Bb1 : Bb0;

        #pragma unroll
        for (int kk = 0; kk < 6; kk++) {
            const int k = kk * 16;
            uint32_t a[2][4];
            #pragma unroll
            for (int m = 0; m < 2; m++)
                ldm_x4(a[m][0], a[m][1], a[m][2], a[m][3],
                       abase + ((uint32_t)((wm * 32 + m * 16 + (lane & 15)) * 104
                                           + k + (lane >> 4) * 8) << 1));
            #pragma unroll
            for (int g = 0; g < 3; g++) {
                uint32_t b0, b1, b2r, b3;
                ldm_x4(b0, b1, b2r, b3,
                       bbase + ((uint32_t)((wn * 48 + g * 16 + (lane & 15)) * 104
                                           + k + (lane >> 4) * 8) << 1));
                #pragma unroll
                for (int m = 0; m < 2; m++) {
                    mma_bf16(acc[m][g * 2],     a[m][0], a[m][1], a[m][2], a[m][3], b0, b2r);
                    mma_bf16(acc[m][g * 2 + 1], a[m][0], a[m][1], a[m][2], a[m][3], b1, b3);
                }
            }
        }

        if (kc == KCH - 1) {
            const int row0 = tile * 128 + wm * 32;
            const int colb = nb * 96 + wn * 48;
            if (MODE == 1) {
                float* part = reinterpret_cast<float*>(smem + PART_OFF);
                int dda[2], ddb[2];
                #pragma unroll
                for (int m = 0; m < 2; m++) {
                    const int ra = row0 + m * 16 + (lane >> 2);
                    const int rb = ra + 8;
                    #pragma unroll
                    for (int t2 = 0; t2 < 2; t2++) {
                        int row = t2 ? rb : ra;
                        int bi  = row / 3136;
                        int rem = row % 3136;
                        int ww_ = rem / 49, n = rem % 49;
                        int wh = ww_ >> 3, wcl = ww_ & 7;
                        int r7 = n / 7, c7 = n % 7;
                        int hh = wh * 7 + r7 + 3;  if (hh >= 56) hh -= 56;
                        int zz = wcl * 7 + c7 + 3; if (zz >= 56) zz -= 56;
                        int d = bi * 3136 + hh * 56 + zz;
                        if (t2) ddb[m] = d; else dda[m] = d;
                    }
                    float sa = 0.f, qa = 0.f, sb = 0.f, qb = 0.f;
                    #pragma unroll
                    for (int n = 0; n < 6; n++) {
                        const int col = colb + n * 8 + (lane & 3) * 2;
                        float bi0 = __ldg(bias + col), bi1 = __ldg(bias + col + 1);
                        float w00 = acc[m][n][0] + bi0, w01 = acc[m][n][1] + bi1;
                        float w10 = acc[m][n][2] + bi0, w11 = acc[m][n][3] + bi1;
                        size_t oa = (size_t)dda[m] * 96 + col, ob = (size_t)ddb[m] * 96 + col;
                        float2 r0 = *reinterpret_cast<const float2*>(resid + oa);
                        float2 r1 = *reinterpret_cast<const float2*>(resid + ob);
                        w00 += r0.x; w01 += r0.y; w10 += r1.x; w11 += r1.y;
                        *reinterpret_cast<float2*>((float*)outv + oa) = make_float2(w00, w01);
                        *reinterpret_cast<float2*>((float*)outv + ob) = make_float2(w10, w11);
                        acc[m][n][0] = w00; acc[m][n][1] = w01;
                        acc[m][n][2] = w10; acc[m][n][3] = w11;
                        sa += w00 + w01; qa += w00 * w00 + w01 * w01;
                        sb += w10 + w11; qb += w10 * w10 + w11 * w11;
                    }
                    sa += __shfl_xor_sync(0xffffffffu, sa, 1); sa += __shfl_xor_sync(0xffffffffu, sa, 2);
                    qa += __shfl_xor_sync(0xffffffffu, qa, 1); qa += __shfl_xor_sync(0xffffffffu, qa, 2);
                    sb += __shfl_xor_sync(0xffffffffu, sb, 1); sb += __shfl_xor_sync(0xffffffffu, sb, 2);
                    qb += __shfl_xor_sync(0xffffffffu, qb, 1); qb += __shfl_xor_sync(0xffffffffu, qb, 2);
                    if ((lane & 3) == 0) {
                        int lra = wm * 32 + m * 16 + (lane >> 2);
                        part[(wn * 128 + lra) * 2]         = sa;
                        part[(wn * 128 + lra) * 2 + 1]     = qa;
                        part[(wn * 128 + lra + 8) * 2]     = sb;
                        part[(wn * 128 + lra + 8) * 2 + 1] = qb;
                    }
                }
                __syncthreads();
                #pragma unroll
                for (int m = 0; m < 2; m++) {
                    int lra = wm * 32 + m * 16 + (lane >> 2);
                    float sA = part[lra * 2] + part[(128 + lra) * 2];
                    float qA = part[lra * 2 + 1] + part[(128 + lra) * 2 + 1];
                    float sB = part[(lra + 8) * 2] + part[(128 + lra + 8) * 2];
                    float qB = part[(lra + 8) * 2 + 1] + part[(128 + lra + 8) * 2 + 1];
                    float mA = sA * (1.0f / 96.0f);
                    float rA = rsqrtf(qA * (1.0f / 96.0f) - mA * mA + 1e-5f);
                    float mB = sB * (1.0f / 96.0f);
                    float rB = rsqrtf(qB * (1.0f / 96.0f) - mB * mB + 1e-5f);
                    #pragma unroll
                    for (int n = 0; n < 6; n++) {
                        const int col = colb + n * 8 + (lane & 3) * 2;
                        float g0 = __ldg(g2 + col), g1 = __ldg(g2 + col + 1);
                        float c0 = __ldg(b2 + col), c1 = __ldg(b2 + col + 1);
                        float l00 = (acc[m][n][0] - mA) * rA * g0 + c0;
                        float l01 = (acc[m][n][1] - mA) * rA * g1 + c1;
                        float l10 = (acc[m][n][2] - mB) * rB * g0 + c0;
                        float l11 = (acc[m][n][3] - mB) * rB * g1 + c1;
                        *reinterpret_cast<uint32_t*>(ln2out + (size_t)dda[m] * 96 + col) = packbf(l00, l01);
                        *reinterpret_cast<uint32_t*>(ln2out + (size_t)ddb[m] * 96 + col) = packbf(l10, l11);
                    }
                }
            } else {
                #pragma unroll
                for (int m = 0; m < 2; m++) {
                    const int ra = row0 + m * 16 + (lane >> 2);
                    const int rb = ra + 8;
                    #pragma unroll
                    for (int n = 0; n < 6; n++) {
                        const int col = colb + n * 8 + (lane & 3) * 2;
                        float bi0 = __ldg(bias + col), bi1 = __ldg(bias + col + 1);
                        float v00 = acc[m][n][0] + bi0, v01 = acc[m][n][1] + bi1;
                        float v10 = acc[m][n][2] + bi0, v11 = acc[m][n][3] + bi1;
                        if (MODE == 0) {
                            if (col < 96) { v00 *= QSCALE; v01 *= QSCALE; v10 *= QSCALE; v11 *= QSCALE; }
                            __nv_bfloat16* out = (__nv_bfloat16*)outv;
                            *reinterpret_cast<uint32_t*>(out + (size_t)ra * NOUT + col) = packbf(v00, v01);
                            *reinterpret_cast<uint32_t*>(out + (size_t)rb * NOUT + col) = packbf(v10, v11);
                        } else if (MODE == 2) {
                            v00 = 0.5f * v00 * (1.0f + erff(v00 * 0.70710678118654752f));
                            v01 = 0.5f * v01 * (1.0f + erff(v01 * 0.70710678118654752f));
                            v10 = 0.5f * v10 * (1.0f + erff(v10 * 0.70710678118654752f));
                            v11 = 0.5f * v11 * (1.0f + erff(v11 * 0.70710678118654752f));
                            __nv_bfloat16* out = (__nv_bfloat16*)outv;
                            *reinterpret_cast<uint32_t*>(out + (size_t)ra * NOUT + col) = packbf(v00, v01);
                            *reinterpret_cast<uint32_t*>(out + (size_t)rb * NOUT + col) = packbf(v10, v11);
                        } else {
                            float* out = (float*)outv;
                            size_t oa = (size_t)ra * 96 + col, ob = (size_t)rb * 96 + col;
                            float2 r0 = *reinterpret_cast<const float2*>(out + oa);
                            float2 r1 = *reinterpret_cast<const float2*>(out + ob);
                            r0.x += v00; r0.y += v01; r1.x += v10; r1.y += v11;
                            *reinterpret_cast<float2*>(out + oa) = r0;
                            *reinterpret_cast<float2*>(out + ob) = r1;
                        }
                    }
                }
            }
        }
        __syncthreads();
    }
}

// ---------------------------------------------------------------------------
// Tensor-core windowed attention (bias table version, m-tiles serialized)
// ---------------------------------------------------------------------------
__global__ void __launch_bounds__(192, 3)
attn_tc(const __nv_bfloat16* __restrict__ qkv, const __nv_bfloat16* __restrict__ btab,
        __nv_bfloat16* __restrict__ out) {
    extern __shared__ char ash[];
    __nv_bfloat16* Qs = reinterpret_cast<__nv_bfloat16*>(ash);
    __nv_bfloat16* Ks = Qs + 7680;
    __nv_bfloat16* Vs = Ks + 7680;

    const uint32_t qb = smem_u32(Qs), kb = smem_u32(Ks), vb = smem_u32(Vs);
    const int wb  = blockIdx.x;
    const int t0  = wb * 49;
    const int tid = threadIdx.x;
    const int lane = tid & 31;
    const int wid  = tid >> 5;

    for (int idx = tid; idx < 64 * 144; idx += 192) {
        int j = idx / 144, w = idx % 144;
        int arr = w / 48, ww = w % 48;
        int h = ww / 16, d2 = ww % 16;
        uint32_t val = 0;
        if (j < 49)
            val = reinterpret_cast<const uint32_t*>(qkv + (size_t)(t0 + j) * 288)[w];
        uint32_t off = (uint32_t)(h * 2560 + j * 40 + d2 * 2);
        __nv_bfloat16* base = (arr == 0) ? Qs : (arr == 1) ? Ks : Vs;
        *reinterpret_cast<uint32_t*>(base + off) = val;
    }
    __syncthreads();

    const int h  = wid >> 1;
    const int mh = wid & 1;
    const uint32_t qh = qb + (uint32_t)h * 5120;
    const uint32_t kh = kb + (uint32_t)h * 5120;
    const uint32_t vh = vb + (uint32_t)h * 5120;

    const int w_   = wb & 63;
    const int cls  = ((w_ >> 3) == 7 ? 2 : 0) | ((w_ & 7) == 7 ? 1 : 0);
    const __nv_bfloat16* bt = btab + ((size_t)(cls * 3 + h) << 12);

    #pragma unroll
    for (int mt = 0; mt < 2; mt++) {
        const int rbase = mh * 32 + mt * 16;

        float c[8][4];
        #pragma unroll
        for (int n = 0; n < 8; n++)
            #pragma unroll
            for (int v = 0; v < 4; v++) c[n][v] = 0.0f;

        #pragma unroll
        for (int kk = 0; kk < 2; kk++) {
            uint32_t qa0, qa1, qa2, qa3;
            ldm_x4(qa0, qa1, qa2, qa3,
                   qh + ((uint32_t)((rbase + (lane & 15)) * 40 + kk * 16 + (lane >> 4) * 8) << 1));
            #pragma unroll
            for (int np = 0; np < 4; np++) {
                uint32_t b0, b1, b2, b3;
                ldm_x4(b0, b1, b2, b3,
                       kh + ((uint32_t)((np * 16 + (lane & 15)) * 40 + kk * 16 + (lane >> 4) * 8) << 1));
                mma_bf16(c[np * 2],     qa0, qa1, qa2, qa3, b0, b2);
                mma_bf16(c[np * 2 + 1], qa0, qa1, qa2, qa3, b1, b3);
            }
        }

        const int i0 = rbase + (lane >> 2);
        const uint32_t* br0 = reinterpret_cast<const uint32_t*>(bt + i0 * 64) + (lane & 3);
        const uint32_t* br1 = reinterpret_cast<const uint32_t*>(bt + (i0 + 8) * 64) + (lane & 3);
        #pragma unroll
        for (int nt = 0; nt < 8; nt++) {
            uint32_t w0 = __ldg(br0 + nt * 4);
            uint32_t w1 = __ldg(br1 + nt * 4);
            float2 f0 = __bfloat1622float2(*reinterpret_cast<__nv_bfloat162*>(&w0));
            float2 f1 = __bfloat1622float2(*reinterpret_cast<__nv_bfloat162*>(&w1));
            c[nt][0] += f0.x; c[nt][1] += f0.y;
            c[nt][2] += f1.x; c[nt][3] += f1.y;
        }

        #pragma unroll
        for (int p = 0; p < 2; p++) {
            float mx = -1e30f;
            #pragma unroll
            for (int nt = 0; nt < 8; nt++) {
                mx = fmaxf(mx, c[nt][p * 2]);
                mx = fmaxf(mx, c[nt][p * 2 + 1]);
            }
            mx = fmaxf(mx, __shfl_xor_sync(0xffffffffu, mx, 1));
            mx = fmaxf(mx, __shfl_xor_sync(0xffffffffu, mx, 2));
            float sum = 0.0f;
            #pragma unroll
            for (int nt = 0; nt < 8; nt++) {
                float e0 = __expf(c[nt][p * 2]     - mx);
                float e1 = __expf(c[nt][p * 2 + 1] - mx);
                c[nt][p * 2] = e0; c[nt][p * 2 + 1] = e1;
                sum += e0 + e1;
            }
            sum += __shfl_xor_sync(0xffffffffu, sum, 1);
            sum += __shfl_xor_sync(0xffffffffu, sum, 2);
            float inv = 1.0f / sum;
            #pragma unroll
            for (int nt = 0; nt < 8; nt++) {
                c[nt][p * 2] *= inv; c[nt][p * 2 + 1] *= inv;
            }
        }

        float o[4][4];
        #pragma unroll
        for (int n = 0; n < 4; n++)
            #pragma unroll
            for (int v = 0; v < 4; v++) o[n][v] = 0.0f;

        #pragma unroll
        for (int kk = 0; kk < 4; kk++) {
            uint32_t vf[2][4];
            #pragma unroll
            for (int dh = 0; dh < 2; dh++)
                ldm_x4t(vf[dh][0], vf[dh][1], vf[dh][2], vf[dh][3],
                        vh + ((uint32_t)((kk * 16 + (lane & 7) + ((lane >> 3) & 1) * 8) * 40
                                         + dh * 16 + (lane >> 4) * 8) << 1));
            uint32_t pa0 = packbf(c[2 * kk][0],     c[2 * kk][1]);
            uint32_t pa1 = packbf(c[2 * kk][2],     c[2 * kk][3]);
            uint32_t pa2 = packbf(c[2 * kk + 1][0], c[2 * kk + 1][1]);
            uint32_t pa3 = packbf(c[2 * kk + 1][2], c[2 * kk + 1][3]);
            #pragma unroll
            for (int dn = 0; dn < 4; dn++) {
                uint32_t vb0 = (dn & 1) ? vf[dn >> 1][2] : vf[dn >> 1][0];
                uint32_t vb1 = (dn & 1) ? vf[dn >> 1][3] : vf[dn >> 1][1];
                mma_bf16(o[dn], pa0, pa1, pa2, pa3, vb0, vb1);
            }
        }

        #pragma unroll
        for (int p = 0; p < 2; p++) {
            int i = rbase + (lane >> 2) + p * 8;
            if (i < 49) {
                __nv_bfloat16* orow = out + (size_t)(t0 + i) * 96 + h * 32;
                #pragma unroll
                for (int dn = 0; dn < 4; dn++) {
                    int d = dn * 8 + (lane & 3) * 2;
                    *reinterpret_cast<uint32_t*>(orow + d) = packbf(o[dn][p * 2], o[dn][p * 2 + 1]);
                }
            }
        }
    }
}

// ---------------------------------------------------------------------------
extern "C" void kernel_launch(void* const* d_in, const int* in_sizes, int n_in,
                              void* d_out, int out_size) {
    const float* x      = (const float*)d_in[0];
    const float* n1g    = (const float*)d_in[1];
    const float* n1b    = (const float*)d_in[2];
    const float* qkv_w  = (const float*)d_in[3];
    const float* qkv_b  = (const float*)d_in[4];
    const float* rpb    = (const float*)d_in[5];
    const float* proj_w = (const float*)d_in[6];
    const float* proj_b = (const float*)d_in[7];
    const float* n2g    = (const float*)d_in[8];
    const float* n2b    = (const float*)d_in[9];
    const float* fc1_w  = (const float*)d_in[10];
    const float* fc1_b  = (const float*)d_in[11];
    const float* fc2_w  = (const float*)d_in[12];
    const float* fc2_b  = (const float*)d_in[13];
    float* out = (float*)d_out;

    __nv_bfloat16 *buf1, *buf2, *buf3, *wb, *bt;
    cudaGetSymbolAddress((void**)&buf1, g_buf1);
    cudaGetSymbolAddress((void**)&buf2, g_buf2);
    cudaGetSymbolAddress((void**)&buf3, g_buf3);
    cudaGetSymbolAddress((void**)&wb,   g_wbuf);
    cudaGetSymbolAddress((void**)&bt,   g_bias);

    const int smem_gemm = 2 * 26624 + 2 * 19968;          // 93184
    const int smem_proj = smem_gemm + 2048;               // + LN partials
    const int smem_attn = 3 * 7680 * 2;                   // 46080
    cudaFuncSetAttribute(tc_gemm<0, 96, 1, 288, 3>,  cudaFuncAttributeMaxDynamicSharedMemorySize, smem_gemm);
    cudaFuncSetAttribute(tc_gemm<1, 96, 1, 96, 1>,   cudaFuncAttributeMaxDynamicSharedMemorySize, smem_proj);
    cudaFuncSetAttribute(tc_gemm<2, 96, 1, 384, 4>,  cudaFuncAttributeMaxDynamicSharedMemorySize, smem_gemm);
    cudaFuncSetAttribute(tc_gemm<3, 384, 4, 96, 1>,  cudaFuncAttributeMaxDynamicSharedMemorySize, smem_gemm);
    cudaFuncSetAttribute(attn_tc, cudaFuncAttributeMaxDynamicSharedMemorySize, smem_attn);

    // 0) weights fp32 -> bf16; combined bias table
    wconv<<<432, 256>>>(qkv_w, proj_w, fc1_w, fc2_w, wb);
    bias_prep<<<192, 256>>>(rpb, bt);
    // 1) QKV GEMM with FUSED LN1 + shift gather (x via resid, LN via g2/b2)
    //    -> buf1 bf16 [T,288]
    tc_gemm<0, 96, 1, 288, 3><<<GPERS, 256, smem_gemm>>>(nullptr, wb + WOFF_QKV, qkv_b, buf1, x, n1g, n1b, nullptr);
    // 2) tensor-core windowed attention -> buf2 bf16 [T,96]
    attn_tc<<<4096, 192, smem_attn>>>(buf1, bt, buf2);
    // 3) proj GEMM + window reverse + unshift + residual + fused LN2
    //    -> d_out fp32 [T,96], buf3 bf16 LN2 [T,96]
    tc_gemm<1, 96, 1, 96, 1><<<GPERS, 256, smem_proj>>>(buf2, wb + WOFF_PROJ, proj_b, out, x, n2g, n2b, buf3);
    // 4) FC1 + GELU (A resident across 4 n-chunks) -> buf1 bf16 [T,384]
    tc_gemm<2, 96, 1, 384, 4><<<GPERS, 256, smem_gemm>>>(buf3, wb + WOFF_FC1, fc1_b, buf1, nullptr, nullptr, nullptr, nullptr);
    // 5) FC2 + accumulate into d_out
    tc_gemm<3, 384, 4, 96, 1><<<GPERS, 256, smem_gemm>>>(buf1, wb + WOFF_FC2, fc2_b, out, nullptr, nullptr, nullptr, nullptr);
}

// round 15
// speedup vs baseline: 1.0870x; 1.0870x over previous
#include <cuda_runtime.h>
#include <cuda_bf16.h>
#include <math.h>
#include <cstdint>

#define TKN    200704
#define QSCALE 0.17677669529663688f
#define GPERS  304              // persistent grid: 2 CTAs/SM x 152 SMs

// Scratch (allocation-free): bf16 activations + pre-converted weights
__device__ __nv_bfloat16 g_buf1[200704 * 384];  // qkv [T,288] then fc1-out [T,384]
__device__ __nv_bfloat16 g_buf2[200704 * 96];   // ln1-out, attn-out [T,96]
__device__ __nv_bfloat16 g_buf3[200704 * 96];   // fused-LN2 out [T,96]
__device__ __nv_bfloat16 g_wbuf[110592];        // qkv_w | proj_w | fc1_w | fc2_w (bf16)
__device__ __nv_bfloat16 g_bias[4 * 3 * 64 * 64]; // combined bias+mask per window class

#define WOFF_QKV  0
#define WOFF_PROJ 27648
#define WOFF_FC1  36864
#define WOFF_FC2  73728

// ---------------------------------------------------------------------------
// PTX helpers
// ---------------------------------------------------------------------------
__device__ __forceinline__ uint32_t smem_u32(const void* p) {
    uint32_t a;
    asm("{ .reg .u64 t; cvta.to.shared.u64 t, %1; cvt.u32.u64 %0, t; }" : "=r"(a) : "l"(p));
    return a;
}
__device__ __forceinline__ void cp16(uint32_t dst, const void* src) {
    asm volatile("cp.async.cg.shared.global [%0], [%1], 16;" :: "r"(dst), "l"(src));
}
#define CP_COMMIT() asm volatile("cp.async.commit_group;" ::: "memory")
__device__ __forceinline__ void ldm_x4(uint32_t& r0, uint32_t& r1, uint32_t& r2, uint32_t& r3,
                                       uint32_t addr) {
    asm volatile("ldmatrix.sync.aligned.m8n8.x4.shared.b16 {%0,%1,%2,%3}, [%4];"
                 : "=r"(r0), "=r"(r1), "=r"(r2), "=r"(r3) : "r"(addr));
}
__device__ __forceinline__ void ldm_x4t(uint32_t& r0, uint32_t& r1, uint32_t& r2, uint32_t& r3,
                                        uint32_t addr) {
    asm volatile("ldmatrix.sync.aligned.m8n8.x4.trans.shared.b16 {%0,%1,%2,%3}, [%4];"
                 : "=r"(r0), "=r"(r1), "=r"(r2), "=r"(r3) : "r"(addr));
}
__device__ __forceinline__ void mma_bf16(float* c, uint32_t a0, uint32_t a1, uint32_t a2,
                                         uint32_t a3, uint32_t b0, uint32_t b1) {
    asm volatile("mma.sync.aligned.m16n8k16.row.col.f32.bf16.bf16.f32 "
                 "{%0,%1,%2,%3}, {%4,%5,%6,%7}, {%8,%9}, {%0,%1,%2,%3};"
                 : "+f"(c[0]), "+f"(c[1]), "+f"(c[2]), "+f"(c[3])
                 : "r"(a0), "r"(a1), "r"(a2), "r"(a3), "r"(b0), "r"(b1));
}
__device__ __forceinline__ uint32_t packbf(float a, float b) {
    __nv_bfloat162 h = __floats2bfloat162_rn(a, b);
    return *reinterpret_cast<uint32_t*>(&h);
}

// ---------------------------------------------------------------------------
// Weight pre-convert fp32 -> bf16
// ---------------------------------------------------------------------------
__global__ void wconv(const float* __restrict__ a, const float* __restrict__ b,
                      const float* __restrict__ c, const float* __restrict__ d,
                      __nv_bfloat16* __restrict__ o) {
    int i = blockIdx.x * 256 + threadIdx.x;
    if (i < 27648)       o[i] = __float2bfloat16(a[i]);
    else if (i < 36864)  o[i] = __float2bfloat16(b[i - 27648]);
    else if (i < 73728)  o[i] = __float2bfloat16(c[i - 36864]);
    else if (i < 110592) o[i] = __float2bfloat16(d[i - 73728]);
}

// ---------------------------------------------------------------------------
// Combined bias table: tab[cls][h][i(64)][j(64)] = rpb + shiftmask, pad -> -1e30
// ---------------------------------------------------------------------------
__device__ __forceinline__ int winlab(int cls, int r, int c) {
    int rh = (cls & 2) ? (r < 4 ? 1 : 2) : 0;
    int rw = (cls & 1) ? (c < 4 ? 1 : 2) : 0;
    return rh * 3 + rw;
}
__global__ void bias_prep(const float* __restrict__ rpb, __nv_bfloat16* __restrict__ tab) {
    int idx = blockIdx.x * 256 + threadIdx.x;
    if (idx >= 4 * 3 * 64 * 64) return;
    int j = idx & 63, i = (idx >> 6) & 63;
    int h = (idx >> 12) % 3, cls = idx >> 12; cls /= 3;
    float v;
    if (j >= 49 || i >= 49) v = -1e30f;
    else {
        int ri = i / 7, ci = i % 7, rj = j / 7, cj = j % 7;
        v = rpb[((ri - rj + 6) * 13 + (ci - cj + 6)) * 3 + h];
        if (winlab(cls, ri, ci) != winlab(cls, rj, cj)) v -= 100.0f;
    }
    tab[idx] = __float2bfloat16(v);
}

// ---------------------------------------------------------------------------
// LN kernel (one warp per token, bf16 out, shift+partition gather)
// ---------------------------------------------------------------------------
__global__ void ln_kernel(const float* __restrict__ x, const float* __restrict__ g,
                          const float* __restrict__ b, __nv_bfloat16* __restrict__ out,
                          int shifted) {
    int warp = (blockIdx.x * blockDim.x + threadIdx.x) >> 5;
    int lane = threadIdx.x & 31;
    if (warp >= TKN) return;
    int src = warp;
    if (shifted) {
        int bi  = warp / 3136;
        int rem = warp % 3136;
        int w   = rem / 49, n = rem % 49;
        int wh = w >> 3, ww = w & 7;
        int r = n / 7, cc = n % 7;
        int sh = wh * 7 + r + 3;  if (sh >= 56) sh -= 56;
        int sw = ww * 7 + cc + 3; if (sw >= 56) sw -= 56;
        src = bi * 3136 + sh * 56 + sw;
    }
    const float* xr = x + (size_t)src * 96;
    float v0 = xr[lane], v1 = xr[lane + 32], v2 = xr[lane + 64];
    float s  = v0 + v1 + v2;
    float s2 = v0 * v0 + v1 * v1 + v2 * v2;
    #pragma unroll
    for (int o = 16; o; o >>= 1) {
        s  += __shfl_xor_sync(0xffffffffu, s,  o);
        s2 += __shfl_xor_sync(0xffffffffu, s2, o);
    }
    float mean = s * (1.0f / 96.0f);
    float var  = s2 * (1.0f / 96.0f) - mean * mean;
    float rs   = rsqrtf(var + 1e-5f);
    __nv_bfloat16* orow = out + (size_t)warp * 96;
    orow[lane]      = __float2bfloat16((v0 - mean) * rs * g[lane]      + b[lane]);
    orow[lane + 32] = __float2bfloat16((v1 - mean) * rs * g[lane + 32] + b[lane + 32]);
    orow[lane + 64] = __float2bfloat16((v2 - mean) * rs * g[lane + 64] + b[lane + 64]);
}

// ---------------------------------------------------------------------------
// Persistent pipelined HMMA GEMM (256 thr, 8 warps 4x2, warp 32x48).
// nb-INNER contiguous unit blocks; A resident across NB n-chunks; 16B cp.async.
// MODE 0: qkv; MODE 1: proj + residual + fused LN2; MODE 2: fc1+GELU;
// MODE 3: fc2 accumulate.
// ---------------------------------------------------------------------------
template <int MODE, int KGLOB, int KCH, int NOUT, int NB>
__global__ void __launch_bounds__(256, 2)
tc_gemm(const __nv_bfloat16* __restrict__ A, const __nv_bfloat16* __restrict__ Wb,
        const float* __restrict__ bias, void* __restrict__ outv,
        const float* __restrict__ resid, const float* __restrict__ g2,
        const float* __restrict__ b2, __nv_bfloat16* __restrict__ ln2out) {
    constexpr int NT = 1568;
    constexpr int NUNITS = NT * NB;
    constexpr int ABYTES = 128 * 104 * 2;
    constexpr int BBYTES = 96 * 104 * 2;
    constexpr int PART_OFF = 2 * ABYTES + 2 * BBYTES;
    extern __shared__ char smem[];
    const uint32_t sbase = smem_u32(smem);
    const uint32_t Ab0 = sbase, Ab1 = sbase + ABYTES;
    const uint32_t Bb0 = sbase + 2 * ABYTES, Bb1 = Bb0 + BBYTES;

    const int tid  = threadIdx.x;
    const int lane = tid & 31;
    const int wid  = tid >> 5;
    const int wm   = wid & 3;
    const int wn   = wid >> 2;

    constexpr int PERCTA = (NUNITS + GPERS - 1) / GPERS;
    const int base    = blockIdx.x * PERCTA;
    int myUnits       = NUNITS - base;
    if (myUnits > PERCTA) myUnits = PERCTA;
    if (myUnits <= 0) return;
    const int mySteps = myUnits * KCH;

    auto issue = [&](int s) {
        const int lu   = s / KCH;
        const int kc   = s % KCH;
        const int u    = base + lu;
        const int tile = u / NB;
        const int nb   = u % NB;
        {
            const __nv_bfloat16* sb = Wb + (size_t)nb * 96 * KGLOB + kc * 96;
            uint32_t db = (s & 1) ? Bb1 : Bb0;
            #pragma unroll
            for (int i = tid; i < 96 * 12; i += 256) {
                int r = i / 12, c = i % 12;
                cp16(db + r * 208 + c * 16, sb + (size_t)r * KGLOB + c * 8);
            }
        }
        bool needA = (KCH > 1) || (u % NB == 0) || (s == 0);
        if (needA) {
            const __nv_bfloat16* sa = A + (size_t)tile * 128 * KGLOB + kc * 96;
            uint32_t da;
            if (KCH > 1) da = (s & 1) ? Ab1 : Ab0;
            else         da = ((tile & 1) ? Ab1 : Ab0);
            #pragma unroll
            for (int i = tid; i < 128 * 12; i += 256) {
                int r = i / 12, c = i % 12;
                cp16(da + r * 208 + c * 16, sa + (size_t)r * KGLOB + c * 8);
            }
        }
    };

    issue(0); CP_COMMIT();

    float acc[2][6][4];

    for (int s = 0; s < mySteps; s++) {
        const int kc   = s % KCH;
        const int u    = base + s / KCH;
        const int tile = u / NB;
        const int nb   = u % NB;
        if (s + 1 < mySteps) {
            issue(s + 1);
            CP_COMMIT();
            asm volatile("cp.async.wait_group 1;" ::: "memory");
        } else {
            asm volatile("cp.async.wait_group 0;" ::: "memory");
        }
        __syncthreads();

        if (kc == 0) {
            #pragma unroll
            for (int m = 0; m < 2; m++)
                #pragma unroll
                for (int n = 0; n < 6; n++)
                    #pragma unroll
                    for (int v = 0; v < 4; v++) acc[m][n][v] = 0.0f;
        }

        const uint32_t abase = (KCH > 1) ? ((s & 1) ? Ab1 : Ab0)
                                         : ((tile & 1) ? Ab1 : Ab0);
        const uint32_t bbase = (s & 1) ? Bb1 : Bb0;

        #pragma unroll
        for (int kk = 0; kk < 6; kk++) {
            const int k = kk * 16;
            uint32_t a[2][4];
            #pragma unroll
            for (int m = 0; m < 2; m++)
                ldm_x4(a[m][0], a[m][1], a[m][2], a[m][3],
                       abase + ((uint32_t)((wm * 32 + m * 16 + (lane & 15)) * 104
                                           + k + (lane >> 4) * 8) << 1));
            #pragma unroll
            for (int g = 0; g < 3; g++) {
                uint32_t b0, b1, b2r, b3;
                ldm_x4(b0, b1, b2r, b3,
                       bbase + ((uint32_t)((wn * 48 + g * 16 + (lane & 15)) * 104
                                           + k + (lane >> 4) * 8) << 1));
                #pragma unroll
                for (int m = 0; m < 2; m++) {
                    mma_bf16(acc[m][g * 2],     a[m][0], a[m][1], a[m][2], a[m][3], b0, b2r);
                    mma_bf16(acc[m][g * 2 + 1], a[m][0], a[m][1], a[m][2], a[m][3], b1, b3);
                }
            }
        }

        if (kc == KCH - 1) {
            const int row0 = tile * 128 + wm * 32;
            const int colb = nb * 96 + wn * 48;
            if (MODE == 1) {
                float* part = reinterpret_cast<float*>(smem + PART_OFF);
                int dda[2], ddb[2];
                #pragma unroll
                for (int m = 0; m < 2; m++) {
                    const int ra = row0 + m * 16 + (lane >> 2);
                    const int rb = ra + 8;
                    #pragma unroll
                    for (int t2 = 0; t2 < 2; t2++) {
                        int row = t2 ? rb : ra;
                        int bi  = row / 3136;
                        int rem = row % 3136;
                        int ww_ = rem / 49, n = rem % 49;
                        int wh = ww_ >> 3, wcl = ww_ & 7;
                        int r7 = n / 7, c7 = n % 7;
                        int hh = wh * 7 + r7 + 3;  if (hh >= 56) hh -= 56;
                        int zz = wcl * 7 + c7 + 3; if (zz >= 56) zz -= 56;
                        int d = bi * 3136 + hh * 56 + zz;
                        if (t2) ddb[m] = d; else dda[m] = d;
                    }
                    float sa = 0.f, qa = 0.f, sb = 0.f, qb = 0.f;
                    #pragma unroll
                    for (int n = 0; n < 6; n++) {
                        const int col = colb + n * 8 + (lane & 3) * 2;
                        float bi0 = __ldg(bias + col), bi1 = __ldg(bias + col + 1);
                        float w00 = acc[m][n][0] + bi0, w01 = acc[m][n][1] + bi1;
                        float w10 = acc[m][n][2] + bi0, w11 = acc[m][n][3] + bi1;
                        size_t oa = (size_t)dda[m] * 96 + col, ob = (size_t)ddb[m] * 96 + col;
                        float2 r0 = *reinterpret_cast<const float2*>(resid + oa);
                        float2 r1 = *reinterpret_cast<const float2*>(resid + ob);
                        w00 += r0.x; w01 += r0.y; w10 += r1.x; w11 += r1.y;
                        *reinterpret_cast<float2*>((float*)outv + oa) = make_float2(w00, w01);
                        *reinterpret_cast<float2*>((float*)outv + ob) = make_float2(w10, w11);
                        acc[m][n][0] = w00; acc[m][n][1] = w01;
                        acc[m][n][2] = w10; acc[m][n][3] = w11;
                        sa += w00 + w01; qa += w00 * w00 + w01 * w01;
                        sb += w10 + w11; qb += w10 * w10 + w11 * w11;
                    }
                    sa += __shfl_xor_sync(0xffffffffu, sa, 1); sa += __shfl_xor_sync(0xffffffffu, sa, 2);
                    qa += __shfl_xor_sync(0xffffffffu, qa, 1); qa += __shfl_xor_sync(0xffffffffu, qa, 2);
                    sb += __shfl_xor_sync(0xffffffffu, sb, 1); sb += __shfl_xor_sync(0xffffffffu, sb, 2);
                    qb += __shfl_xor_sync(0xffffffffu, qb, 1); qb += __shfl_xor_sync(0xffffffffu, qb, 2);
                    if ((lane & 3) == 0) {
                        int lra = wm * 32 + m * 16 + (lane >> 2);
                        part[(wn * 128 + lra) * 2]         = sa;
                        part[(wn * 128 + lra) * 2 + 1]     = qa;
                        part[(wn * 128 + lra + 8) * 2]     = sb;
                        part[(wn * 128 + lra + 8) * 2 + 1] = qb;
                    }
                }
                __syncthreads();
                #pragma unroll
                for (int m = 0; m < 2; m++) {
                    int lra = wm * 32 + m * 16 + (lane >> 2);
                    float sA = part[lra * 2] + part[(128 + lra) * 2];
                    float qA = part[lra * 2 + 1] + part[(128 + lra) * 2 + 1];
                    float sB = part[(lra + 8) * 2] + part[(128 + lra + 8) * 2];
                    float qB = part[(lra + 8) * 2 + 1] + part[(128 + lra + 8) * 2 + 1];
                    float mA = sA * (1.0f / 96.0f);
                    float rA = rsqrtf(qA * (1.0f / 96.0f) - mA * mA + 1e-5f);
                    float mB = sB * (1.0f / 96.0f);
                    float rB = rsqrtf(qB * (1.0f / 96.0f) - mB * mB + 1e-5f);
                    #pragma unroll
                    for (int n = 0; n < 6; n++) {
                        const int col = colb + n * 8 + (lane & 3) * 2;
                        float g0 = __ldg(g2 + col), g1 = __ldg(g2 + col + 1);
                        float c0 = __ldg(b2 + col), c1 = __ldg(b2 + col + 1);
                        float l00 = (acc[m][n][0] - mA) * rA * g0 + c0;
                        float l01 = (acc[m][n][1] - mA) * rA * g1 + c1;
                        float l10 = (acc[m][n][2] - mB) * rB * g0 + c0;
                        float l11 = (acc[m][n][3] - mB) * rB * g1 + c1;
                        *reinterpret_cast<uint32_t*>(ln2out + (size_t)dda[m] * 96 + col) = packbf(l00, l01);
                        *reinterpret_cast<uint32_t*>(ln2out + (size_t)ddb[m] * 96 + col) = packbf(l10, l11);
                    }
                }
            } else {
                #pragma unroll
                for (int m = 0; m < 2; m++) {
                    const int ra = row0 + m * 16 + (lane >> 2);
                    const int rb = ra + 8;
                    #pragma unroll
                    for (int n = 0; n < 6; n++) {
                        const int col = colb + n * 8 + (lane & 3) * 2;
                        float bi0 = __ldg(bias + col), bi1 = __ldg(bias + col + 1);
                        float v00 = acc[m][n][0] + bi0, v01 = acc[m][n][1] + bi1;
                        float v10 = acc[m][n][2] + bi0, v11 = acc[m][n][3] + bi1;
                        if (MODE == 0) {
                            if (col < 96) { v00 *= QSCALE; v01 *= QSCALE; v10 *= QSCALE; v11 *= QSCALE; }
                            __nv_bfloat16* out = (__nv_bfloat16*)outv;
                            *reinterpret_cast<uint32_t*>(out + (size_t)ra * NOUT + col) = packbf(v00, v01);
                            *reinterpret_cast<uint32_t*>(out + (size_t)rb * NOUT + col) = packbf(v10, v11);
                        } else if (MODE == 2) {
                            v00 = 0.5f * v00 * (1.0f + erff(v00 * 0.70710678118654752f));
                            v01 = 0.5f * v01 * (1.0f + erff(v01 * 0.70710678118654752f));
                            v10 = 0.5f * v10 * (1.0f + erff(v10 * 0.70710678118654752f));
                            v11 = 0.5f * v11 * (1.0f + erff(v11 * 0.70710678118654752f));
                            __nv_bfloat16* out = (__nv_bfloat16*)outv;
                            *reinterpret_cast<uint32_t*>(out + (size_t)ra * NOUT + col) = packbf(v00, v01);
                            *reinterpret_cast<uint32_t*>(out + (size_t)rb * NOUT + col) = packbf(v10, v11);
                        } else {
                            float* out = (float*)outv;
                            size_t oa = (size_t)ra * 96 + col, ob = (size_t)rb * 96 + col;
                            float2 r0 = *reinterpret_cast<const float2*>(out + oa);
                            float2 r1 = *reinterpret_cast<const float2*>(out + ob);
                            r0.x += v00; r0.y += v01; r1.x += v10; r1.y += v11;
                            *reinterpret_cast<float2*>(out + oa) = r0;
                            *reinterpret_cast<float2*>(out + ob) = r1;
                        }
                    }
                }
            }
        }
        __syncthreads();
    }
}

// ---------------------------------------------------------------------------
// Tensor-core windowed attention. Division-free vectorized loader:
// thread t -> (row j = t/3, array = t%3), 12x uint4 per thread.
// ---------------------------------------------------------------------------
__global__ void __launch_bounds__(192, 3)
attn_tc(const __nv_bfloat16* __restrict__ qkv, const __nv_bfloat16* __restrict__ btab,
        __nv_bfloat16* __restrict__ out) {
    extern __shared__ char ash[];
    __nv_bfloat16* Qs = reinterpret_cast<__nv_bfloat16*>(ash);
    __nv_bfloat16* Ks = Qs + 7680;
    __nv_bfloat16* Vs = Ks + 7680;

    const uint32_t qb = smem_u32(Qs), kb = smem_u32(Ks), vb = smem_u32(Vs);
    const int wb  = blockIdx.x;
    const int t0  = wb * 49;
    const int tid = threadIdx.x;
    const int lane = tid & 31;
    const int wid  = tid >> 5;

    // ---- loader: j = tid/3 (0..63), arr = tid%3 (Q/K/V segment) ----
    {
        const int j   = tid / 3;
        const int arr = tid - j * 3;
        __nv_bfloat16* basep = (arr == 0) ? Qs : (arr == 1) ? Ks : Vs;
        if (j < 49) {
            const uint4* src = reinterpret_cast<const uint4*>(qkv + (size_t)(t0 + j) * 288 + arr * 96);
            #pragma unroll
            for (int h = 0; h < 3; h++) {
                uint4 v0 = src[h * 4 + 0], v1 = src[h * 4 + 1];
                uint4 v2 = src[h * 4 + 2], v3 = src[h * 4 + 3];
                uint4* dst = reinterpret_cast<uint4*>(basep + h * 2560 + j * 40);
                dst[0] = v0; dst[1] = v1; dst[2] = v2; dst[3] = v3;
            }
        } else {
            uint4 z = make_uint4(0u, 0u, 0u, 0u);
            #pragma unroll
            for (int h = 0; h < 3; h++) {
                uint4* dst = reinterpret_cast<uint4*>(basep + h * 2560 + j * 40);
                dst[0] = z; dst[1] = z; dst[2] = z; dst[3] = z;
            }
        }
    }
    __syncthreads();

    const int h  = wid >> 1;
    const int mh = wid & 1;
    const uint32_t qh = qb + (uint32_t)h * 5120;
    const uint32_t kh = kb + (uint32_t)h * 5120;
    const uint32_t vh = vb + (uint32_t)h * 5120;

    const int w_   = wb & 63;
    const int cls  = ((w_ >> 3) == 7 ? 2 : 0) | ((w_ & 7) == 7 ? 1 : 0);
    const __nv_bfloat16* bt = btab + ((size_t)(cls * 3 + h) << 12);

    #pragma unroll
    for (int mt = 0; mt < 2; mt++) {
        const int rbase = mh * 32 + mt * 16;

        float c[8][4];
        #pragma unroll
        for (int n = 0; n < 8; n++)
            #pragma unroll
            for (int v = 0; v < 4; v++) c[n][v] = 0.0f;

        #pragma unroll
        for (int kk = 0; kk < 2; kk++) {
            uint32_t qa0, qa1, qa2, qa3;
            ldm_x4(qa0, qa1, qa2, qa3,
                   qh + ((uint32_t)((rbase + (lane & 15)) * 40 + kk * 16 + (lane >> 4) * 8) << 1));
            #pragma unroll
            for (int np = 0; np < 4; np++) {
                uint32_t b0, b1, b2, b3;
                ldm_x4(b0, b1, b2, b3,
                       kh + ((uint32_t)((np * 16 + (lane & 15)) * 40 + kk * 16 + (lane >> 4) * 8) << 1));
                mma_bf16(c[np * 2],     qa0, qa1, qa2, qa3, b0, b2);
                mma_bf16(c[np * 2 + 1], qa0, qa1, qa2, qa3, b1, b3);
            }
        }

        const int i0 = rbase + (lane >> 2);
        const uint32_t* br0 = reinterpret_cast<const uint32_t*>(bt + i0 * 64) + (lane & 3);
        const uint32_t* br1 = reinterpret_cast<const uint32_t*>(bt + (i0 + 8) * 64) + (lane & 3);
        #pragma unroll
        for (int nt = 0; nt < 8; nt++) {
            uint32_t w0 = __ldg(br0 + nt * 4);
            uint32_t w1 = __ldg(br1 + nt * 4);
            float2 f0 = __bfloat1622float2(*reinterpret_cast<__nv_bfloat162*>(&w0));
            float2 f1 = __bfloat1622float2(*reinterpret_cast<__nv_bfloat162*>(&w1));
            c[nt][0] += f0.x; c[nt][1] += f0.y;
            c[nt][2] += f1.x; c[nt][3] += f1.y;
        }

        #pragma unroll
        for (int p = 0; p < 2; p++) {
            float mx = -1e30f;
            #pragma unroll
            for (int nt = 0; nt < 8; nt++) {
                mx = fmaxf(mx, c[nt][p * 2]);
                mx = fmaxf(mx, c[nt][p * 2 + 1]);
            }
            mx = fmaxf(mx, __shfl_xor_sync(0xffffffffu, mx, 1));
            mx = fmaxf(mx, __shfl_xor_sync(0xffffffffu, mx, 2));
            float sum = 0.0f;
            #pragma unroll
            for (int nt = 0; nt < 8; nt++) {
                float e0 = __expf(c[nt][p * 2]     - mx);
                float e1 = __expf(c[nt][p * 2 + 1] - mx);
                c[nt][p * 2] = e0; c[nt][p * 2 + 1] = e1;
                sum += e0 + e1;
            }
            sum += __shfl_xor_sync(0xffffffffu, sum, 1);
            sum += __shfl_xor_sync(0xffffffffu, sum, 2);
            float inv = 1.0f / sum;
            #pragma unroll
            for (int nt = 0; nt < 8; nt++) {
                c[nt][p * 2] *= inv; c[nt][p * 2 + 1] *= inv;
            }
        }

        float o[4][4];
        #pragma unroll
        for (int n = 0; n < 4; n++)
            #pragma unroll
            for (int v = 0; v < 4; v++) o[n][v] = 0.0f;

        #pragma unroll
        for (int kk = 0; kk < 4; kk++) {
            uint32_t vf[2][4];
            #pragma unroll
            for (int dh = 0; dh < 2; dh++)
                ldm_x4t(vf[dh][0], vf[dh][1], vf[dh][2], vf[dh][3],
                        vh + ((uint32_t)((kk * 16 + (lane & 7) + ((lane >> 3) & 1) * 8) * 40
                                         + dh * 16 + (lane >> 4) * 8) << 1));
            uint32_t pa0 = packbf(c[2 * kk][0],     c[2 * kk][1]);
            uint32_t pa1 = packbf(c[2 * kk][2],     c[2 * kk][3]);
            uint32_t pa2 = packbf(c[2 * kk + 1][0], c[2 * kk + 1][1]);
            uint32_t pa3 = packbf(c[2 * kk + 1][2], c[2 * kk + 1][3]);
            #pragma unroll
            for (int dn = 0; dn < 4; dn++) {
                uint32_t vb0 = (dn & 1) ? vf[dn >> 1][2] : vf[dn >> 1][0];
                uint32_t vb1 = (dn & 1) ? vf[dn >> 1][3] : vf[dn >> 1][1];
                mma_bf16(o[dn], pa0, pa1, pa2, pa3, vb0, vb1);
            }
        }

        #pragma unroll
        for (int p = 0; p < 2; p++) {
            int i = rbase + (lane >> 2) + p * 8;
            if (i < 49) {
                __nv_bfloat16* orow = out + (size_t)(t0 + i) * 96 + h * 32;
                #pragma unroll
                for (int dn = 0; dn < 4; dn++) {
                    int d = dn * 8 + (lane & 3) * 2;
                    *reinterpret_cast<uint32_t*>(orow + d) = packbf(o[dn][p * 2], o[dn][p * 2 + 1]);
                }
            }
        }
    }
}

// ---------------------------------------------------------------------------
extern "C" void kernel_launch(void* const* d_in, const int* in_sizes, int n_in,
                              void* d_out, int out_size) {
    const float* x      = (const float*)d_in[0];
    const float* n1g    = (const float*)d_in[1];
    const float* n1b    = (const float*)d_in[2];
    const float* qkv_w  = (const float*)d_in[3];
    const float* qkv_b  = (const float*)d_in[4];
    const float* rpb    = (const float*)d_in[5];
    const float* proj_w = (const float*)d_in[6];
    const float* proj_b = (const float*)d_in[7];
    const float* n2g    = (const float*)d_in[8];
    const float* n2b    = (const float*)d_in[9];
    const float* fc1_w  = (const float*)d_in[10];
    const float* fc1_b  = (const float*)d_in[11];
    const float* fc2_w  = (const float*)d_in[12];
    const float* fc2_b  = (const float*)d_in[13];
    float* out = (float*)d_out;

    __nv_bfloat16 *buf1, *buf2, *buf3, *wb, *bt;
    cudaGetSymbolAddress((void**)&buf1, g_buf1);
    cudaGetSymbolAddress((void**)&buf2, g_buf2);
    cudaGetSymbolAddress((void**)&buf3, g_buf3);
    cudaGetSymbolAddress((void**)&wb,   g_wbuf);
    cudaGetSymbolAddress((void**)&bt,   g_bias);

    const int smem_gemm = 2 * 26624 + 2 * 19968;          // 93184
    const int smem_proj = smem_gemm + 2048;               // + LN partials
    const int smem_attn = 3 * 7680 * 2;                   // 46080
    cudaFuncSetAttribute(tc_gemm<0, 96, 1, 288, 3>,  cudaFuncAttributeMaxDynamicSharedMemorySize, smem_gemm);
    cudaFuncSetAttribute(tc_gemm<1, 96, 1, 96, 1>,   cudaFuncAttributeMaxDynamicSharedMemorySize, smem_proj);
    cudaFuncSetAttribute(tc_gemm<2, 96, 1, 384, 4>,  cudaFuncAttributeMaxDynamicSharedMemorySize, smem_gemm);
    cudaFuncSetAttribute(tc_gemm<3, 384, 4, 96, 1>,  cudaFuncAttributeMaxDynamicSharedMemorySize, smem_gemm);
    cudaFuncSetAttribute(attn_tc, cudaFuncAttributeMaxDynamicSharedMemorySize, smem_attn);

    // 0) weights fp32 -> bf16; combined bias table
    wconv<<<432, 256>>>(qkv_w, proj_w, fc1_w, fc2_w, wb);
    bias_prep<<<192, 256>>>(rpb, bt);
    // 1) LN1 + shift + window partition -> buf2 bf16 [T,96]
    ln_kernel<<<TKN / 8, 256>>>(x, n1g, n1b, buf2, 1);
    // 2) QKV GEMM (q pre-scaled, A resident across 3 n-chunks) -> buf1 bf16 [T,288]
    tc_gemm<0, 96, 1, 288, 3><<<GPERS, 256, smem_gemm>>>(buf2, wb + WOFF_QKV, qkv_b, buf1, nullptr, nullptr, nullptr, nullptr);
    // 3) tensor-core windowed attention -> buf2 bf16 [T,96]
    attn_tc<<<4096, 192, smem_attn>>>(buf1, bt, buf2);
    // 4) proj GEMM + window reverse + unshift + residual + fused LN2
    //    -> d_out fp32 [T,96], buf3 bf16 LN2 [T,96]
    tc_gemm<1, 96, 1, 96, 1><<<GPERS, 256, smem_proj>>>(buf2, wb + WOFF_PROJ, proj_b, out, x, n2g, n2b, buf3);
    // 5) FC1 + GELU (A resident across 4 n-chunks) -> buf1 bf16 [T,384]
    tc_gemm<2, 96, 1, 384, 4><<<GPERS, 256, smem_gemm>>>(buf3, wb + WOFF_FC1, fc1_b, buf1, nullptr, nullptr, nullptr, nullptr);
    // 6) FC2 + accumulate into d_out
    tc_gemm<3, 384, 4, 96, 1><<<GPERS, 256, smem_gemm>>>(buf1, wb + WOFF_FC2, fc2_b, out, nullptr, nullptr, nullptr, nullptr);
}